// round 5
// baseline (speedup 1.0000x reference)
#include <cuda_runtime.h>
#include <cuda_bf16.h>
#include <cstdint>

#define NB   16
#define NN   4096
#define NS   1024
#define NK   32
#define NC   64
#define NOUT 128
#define CIN  67          // 3 + 64

// kNN index scratch (static device global; allocation is forbidden)
__device__ int g_idx[NB * NS * NK];

// ---------------------------------------------------------------------------
// Stage 1: farthest point sampling. One block per batch, 1024 threads,
// 4 points/thread register-resident. f32 REDUX max + exact-bit index match.
// ---------------------------------------------------------------------------
__global__ __launch_bounds__(1024, 1)
void fps_kernel(const float* __restrict__ xyz, float* __restrict__ new_xyz)
{
    extern __shared__ float sm[];
    float* xs = sm;
    float* ys = sm + NN;
    float* zs = sm + 2 * NN;
    __shared__ unsigned int wmaxs[32];
    __shared__ int s_idx[2];

    const int b   = blockIdx.x;
    const int tid = threadIdx.x;
    const int lane = tid & 31, wid = tid >> 5;

    const float* gx = xyz + (size_t)b * NN * 3;
    for (int j = tid; j < NN * 3; j += 1024) {
        float v = gx[j];
        int p = j / 3, c = j - p * 3;
        if (c == 0) xs[p] = v; else if (c == 1) ys[p] = v; else zs[p] = v;
    }
    if (tid == 0) { s_idx[0] = 0x7fffffff; s_idx[1] = 0x7fffffff; }
    __syncthreads();

    const int base = tid * 4;
    float px[4], py[4], pz[4], dd[4];
#pragma unroll
    for (int j = 0; j < 4; j++) {
        px[j] = xs[base + j]; py[j] = ys[base + j]; pz[j] = zs[base + j];
        dd[j] = 1e10f;
    }

    int far = 0;
    for (int it = 0; it < NS; it++) {
        const float cx = xs[far], cy = ys[far], cz = zs[far];
        if (tid == 0) {
            float* o = new_xyz + ((size_t)b * NS + it) * 3;
            o[0] = cx; o[1] = cy; o[2] = cz;
        }
        float lm = 0.0f;   // distances are >= 0
#pragma unroll
        for (int j = 0; j < 4; j++) {
            float dx = __fsub_rn(px[j], cx);
            float dy = __fsub_rn(py[j], cy);
            float dz = __fsub_rn(pz[j], cz);
            float d  = __fadd_rn(__fadd_rn(__fmul_rn(dx, dx), __fmul_rn(dy, dy)),
                                 __fmul_rn(dz, dz));
            float nd = fminf(dd[j], d);
            dd[j] = nd;
            lm = fmaxf(lm, nd);
        }
        // warp max (non-negative floats: uint order == float order)
        unsigned wm = __reduce_max_sync(0xffffffffu, __float_as_uint(lm));
        if (lane == 0) wmaxs[wid] = wm;
        __syncthreads();
        // all warps redundantly reduce the 32 warp maxima (no serialization)
        unsigned mv = __reduce_max_sync(0xffffffffu, wmaxs[lane]);
        const float mf = __uint_as_float(mv);
        int cand = 0x7fffffff;
#pragma unroll
        for (int j = 0; j < 4; j++)
            if (dd[j] == mf) cand = min(cand, base + j);
        if (cand != 0x7fffffff) atomicMin(&s_idx[it & 1], cand);
        if (tid == 0) s_idx[(it + 1) & 1] = 0x7fffffff;   // reset next slot (safe: between bars)
        __syncthreads();
        far = s_idx[it & 1];
    }
}

// ---------------------------------------------------------------------------
// Stage 2: kNN. One thread per query; candidates (x,y,z,|p|^2) in smem.
// Candidate loop batched by 4 so LDS.128s pipeline (MLP=4).
// ---------------------------------------------------------------------------
__global__ __launch_bounds__(128, 3)
void knn_kernel(const float* __restrict__ xyz, const float* __restrict__ new_xyz)
{
    extern __shared__ float4 cand[];           // NN entries = 64 KB
    const int b     = blockIdx.x >> 3;         // 8 blocks of 128 queries per batch
    const int chunk = blockIdx.x & 7;
    const int tid   = threadIdx.x;

    const float* gx = xyz + (size_t)b * NN * 3;
    for (int p = tid; p < NN; p += 128) {
        float x = gx[p * 3], y = gx[p * 3 + 1], z = gx[p * 3 + 2];
        float psq = __fadd_rn(__fadd_rn(__fmul_rn(x, x), __fmul_rn(y, y)),
                              __fmul_rn(z, z));
        cand[p] = make_float4(x, y, z, psq);
    }
    __syncthreads();

    const int s = chunk * 128 + tid;
    const float* q = new_xyz + ((size_t)b * NS + s) * 3;
    const float qx = q[0], qy = q[1], qz = q[2];
    const float qsq = __fadd_rn(__fadd_rn(__fmul_rn(qx, qx), __fmul_rn(qy, qy)),
                                __fmul_rn(qz, qz));

    const float INF = __int_as_float(0x7f800000);
    float nd[NK]; int ni[NK];
#pragma unroll
    for (int t = 0; t < NK; t++) { nd[t] = INF; ni[t] = 0x7fffffff; }
    float wd = INF; int wslot = 0;

    for (int j0 = 0; j0 < NN; j0 += 4) {
        float sq[4];
#pragma unroll
        for (int u = 0; u < 4; u++) {
            float4 c = cand[j0 + u];
            float dot = __fadd_rn(__fadd_rn(__fmul_rn(qx, c.x), __fmul_rn(qy, c.y)),
                                  __fmul_rn(qz, c.z));
            sq[u] = __fsub_rn(__fadd_rn(qsq, c.w), __fmul_rn(2.0f, dot));
        }
#pragma unroll
        for (int u = 0; u < 4; u++) {
            if (sq[u] < wd) {   // strict: equal keeps earlier (lower) index, like top_k
#pragma unroll
                for (int t = 0; t < NK; t++)
                    if (t == wslot) { nd[t] = sq[u]; ni[t] = j0 + u; }
                float bw = nd[0]; int bwi = ni[0]; int bslot = 0;
#pragma unroll
                for (int t = 1; t < NK; t++) {
                    bool g = (nd[t] > bw) || (nd[t] == bw && ni[t] > bwi);
                    if (g) { bw = nd[t]; bwi = ni[t]; bslot = t; }
                }
                wd = bw; wslot = bslot;
            }
        }
    }

    int* outp = g_idx + ((size_t)b * NS + s) * NK;
#pragma unroll
    for (int t = 0; t < NK; t++) outp[t] = ni[t];
}

// ---------------------------------------------------------------------------
// Stage 3: gather + 1x1 conv (67->128) + max over K + LayerNorm.
// Thread = output channel; weights in registers (128-reg cap -> NO spills).
// Slot map: 0..2 = xyz_norm, 3 = pad(0), 4+j = voxels[j]  (float4 aligned)
// ---------------------------------------------------------------------------
#define QPB 8
__global__ __launch_bounds__(128, 4)
void embed_kernel(const float* __restrict__ xyz, const float* __restrict__ voxels,
                  const float* __restrict__ w, const float* __restrict__ bias,
                  const float* __restrict__ gamma, const float* __restrict__ beta,
                  const float* __restrict__ new_xyz, float* __restrict__ out)
{
    __shared__ float feat[NK * 68];
    __shared__ float red[4];

    const int tid = threadIdx.x;              // output channel o
    const int lane = tid & 31, wid = tid >> 5;

    float wr[68];
    wr[0] = w[tid * CIN + 0];
    wr[1] = w[tid * CIN + 1];
    wr[2] = w[tid * CIN + 2];
    wr[3] = 0.0f;
#pragma unroll
    for (int j = 0; j < NC; j++) wr[4 + j] = w[tid * CIN + 3 + j];
    const float bo = bias[tid], go = gamma[tid], be = beta[tid];

    const int k    = tid >> 2;   // 0..31 neighbor
    const int quad = tid & 3;    // 0..3

    for (int q = 0; q < QPB; q++) {
        const int gq = blockIdx.x * QPB + q;
        const int b  = gq >> 10;

        const int* ids = g_idx + (size_t)gq * NK;
        const int nidx = ids[k];
        const float4* vrow = (const float4*)(voxels + ((size_t)b * NN + nidx) * NC);
        float4* frow = (float4*)(feat + k * 68);
#pragma unroll
        for (int i = 0; i < 4; i++)
            frow[1 + quad * 4 + i] = vrow[quad * 4 + i];
        if (quad == 0) {
            const float* prow = xyz + ((size_t)b * NN + nidx) * 3;
            const float* qrow = new_xyz + (size_t)gq * 3;
            feat[k * 68 + 0] = __fsub_rn(prow[0], qrow[0]);
            feat[k * 68 + 1] = __fsub_rn(prow[1], qrow[1]);
            feat[k * 68 + 2] = __fsub_rn(prow[2], qrow[2]);
            feat[k * 68 + 3] = 0.0f;
        }
        __syncthreads();

        float m = -__int_as_float(0x7f800000);
        for (int kk = 0; kk < NK; kk += 2) {   // 2 independent acc chains (ILP)
            float a0 = bo, a1 = bo;
            const float4* f0 = (const float4*)(feat + kk * 68);
            const float4* f1 = (const float4*)(feat + kk * 68 + 68);
#pragma unroll
            for (int v = 0; v < 17; v++) {
                float4 p = f0[v];
                float4 r = f1[v];
                a0 = fmaf(p.x, wr[4 * v + 0], a0);
                a1 = fmaf(r.x, wr[4 * v + 0], a1);
                a0 = fmaf(p.y, wr[4 * v + 1], a0);
                a1 = fmaf(r.y, wr[4 * v + 1], a1);
                a0 = fmaf(p.z, wr[4 * v + 2], a0);
                a1 = fmaf(r.z, wr[4 * v + 2], a1);
                a0 = fmaf(p.w, wr[4 * v + 3], a0);
                a1 = fmaf(r.w, wr[4 * v + 3], a1);
            }
            m = fmaxf(m, fmaxf(a0, a1));
        }

        // LayerNorm over 128 channels (one value per thread)
        float v = m;
#pragma unroll
        for (int off = 16; off; off >>= 1) v += __shfl_xor_sync(0xffffffffu, v, off);
        if (lane == 0) red[wid] = v;
        __syncthreads();
        const float mu = (red[0] + red[1] + red[2] + red[3]) * (1.0f / 128.0f);
        const float dm = m - mu;
        __syncthreads();
        float v2 = dm * dm;
#pragma unroll
        for (int off = 16; off; off >>= 1) v2 += __shfl_xor_sync(0xffffffffu, v2, off);
        if (lane == 0) red[wid] = v2;
        __syncthreads();
        const float var = (red[0] + red[1] + red[2] + red[3]) * (1.0f / 128.0f);
        const float y = dm * rsqrtf(var + 1e-5f) * go + be;
        out[(size_t)gq * NOUT + tid] = y;
        __syncthreads();   // protect feat/red for next query
    }
}

// ---------------------------------------------------------------------------
extern "C" void kernel_launch(void* const* d_in, const int* in_sizes, int n_in,
                              void* d_out, int out_size)
{
    const float* xyz    = (const float*)d_in[0];
    const float* voxels = (const float*)d_in[1];
    const float* conv_w = (const float*)d_in[2];
    const float* conv_b = (const float*)d_in[3];
    const float* ln_g   = (const float*)d_in[4];
    const float* ln_b   = (const float*)d_in[5];

    float* out      = (float*)d_out;                    // [B, S, OUT]
    float* new_xyz  = out + (size_t)NB * NS * NOUT;     // [B, S, 3]

    cudaFuncSetAttribute(fps_kernel, cudaFuncAttributeMaxDynamicSharedMemorySize,
                         3 * NN * sizeof(float));
    cudaFuncSetAttribute(knn_kernel, cudaFuncAttributeMaxDynamicSharedMemorySize,
                         NN * sizeof(float4));

    fps_kernel<<<NB, 1024, 3 * NN * sizeof(float)>>>(xyz, new_xyz);
    knn_kernel<<<NB * 8, 128, NN * sizeof(float4)>>>(xyz, new_xyz);
    embed_kernel<<<(NB * NS) / QPB, 128>>>(xyz, voxels, conv_w, conv_b,
                                           ln_g, ln_b, new_xyz, out);
}

// round 6
// speedup vs baseline: 1.7377x; 1.7377x over previous
#include <cuda_runtime.h>
#include <cuda_bf16.h>
#include <cstdint>

#define NB   16
#define NN   4096
#define NS   1024
#define NK   32
#define NC   64
#define NOUT 128
#define CIN  67          // 3 + 64

// kNN index scratch (static device global; allocation is forbidden)
__device__ int g_idx[NB * NS * NK];

// ---------------------------------------------------------------------------
// Stage 1: farthest point sampling. One block per batch, 1024 threads,
// 4 points/thread register-resident. f32 REDUX max + exact-bit index match.
// (unchanged from round 5: 508us measured)
// ---------------------------------------------------------------------------
__global__ __launch_bounds__(1024, 1)
void fps_kernel(const float* __restrict__ xyz, float* __restrict__ new_xyz)
{
    extern __shared__ float sm[];
    float* xs = sm;
    float* ys = sm + NN;
    float* zs = sm + 2 * NN;
    __shared__ unsigned int wmaxs[32];
    __shared__ int s_idx[2];

    const int b   = blockIdx.x;
    const int tid = threadIdx.x;
    const int lane = tid & 31, wid = tid >> 5;

    const float* gx = xyz + (size_t)b * NN * 3;
    for (int j = tid; j < NN * 3; j += 1024) {
        float v = gx[j];
        int p = j / 3, c = j - p * 3;
        if (c == 0) xs[p] = v; else if (c == 1) ys[p] = v; else zs[p] = v;
    }
    if (tid == 0) { s_idx[0] = 0x7fffffff; s_idx[1] = 0x7fffffff; }
    __syncthreads();

    const int base = tid * 4;
    float px[4], py[4], pz[4], dd[4];
#pragma unroll
    for (int j = 0; j < 4; j++) {
        px[j] = xs[base + j]; py[j] = ys[base + j]; pz[j] = zs[base + j];
        dd[j] = 1e10f;
    }

    int far = 0;
    for (int it = 0; it < NS; it++) {
        const float cx = xs[far], cy = ys[far], cz = zs[far];
        if (tid == 0) {
            float* o = new_xyz + ((size_t)b * NS + it) * 3;
            o[0] = cx; o[1] = cy; o[2] = cz;
        }
        float lm = 0.0f;   // distances are >= 0
#pragma unroll
        for (int j = 0; j < 4; j++) {
            float dx = __fsub_rn(px[j], cx);
            float dy = __fsub_rn(py[j], cy);
            float dz = __fsub_rn(pz[j], cz);
            float d  = __fadd_rn(__fadd_rn(__fmul_rn(dx, dx), __fmul_rn(dy, dy)),
                                 __fmul_rn(dz, dz));
            float nd = fminf(dd[j], d);
            dd[j] = nd;
            lm = fmaxf(lm, nd);
        }
        unsigned wm = __reduce_max_sync(0xffffffffu, __float_as_uint(lm));
        if (lane == 0) wmaxs[wid] = wm;
        __syncthreads();
        unsigned mv = __reduce_max_sync(0xffffffffu, wmaxs[lane]);
        const float mf = __uint_as_float(mv);
        int cand = 0x7fffffff;
#pragma unroll
        for (int j = 0; j < 4; j++)
            if (dd[j] == mf) cand = min(cand, base + j);
        if (cand != 0x7fffffff) atomicMin(&s_idx[it & 1], cand);
        if (tid == 0) s_idx[(it + 1) & 1] = 0x7fffffff;
        __syncthreads();
        far = s_idx[it & 1];
    }
}

// ---------------------------------------------------------------------------
// Stage 2: kNN. One thread per query; candidates (x,y,z,|p|^2) in smem.
// Single-candidate insert (small I-footprint) + one-ahead prefetch.
// ---------------------------------------------------------------------------
__global__ __launch_bounds__(128, 3)
void knn_kernel(const float* __restrict__ xyz, const float* __restrict__ new_xyz)
{
    extern __shared__ float4 cand[];           // NN entries = 64 KB
    const int b     = blockIdx.x >> 3;         // 8 blocks of 128 queries per batch
    const int chunk = blockIdx.x & 7;
    const int tid   = threadIdx.x;

    const float* gx = xyz + (size_t)b * NN * 3;
    for (int p = tid; p < NN; p += 128) {
        float x = gx[p * 3], y = gx[p * 3 + 1], z = gx[p * 3 + 2];
        float psq = __fadd_rn(__fadd_rn(__fmul_rn(x, x), __fmul_rn(y, y)),
                              __fmul_rn(z, z));
        cand[p] = make_float4(x, y, z, psq);
    }
    __syncthreads();

    const int s = chunk * 128 + tid;
    const float* q = new_xyz + ((size_t)b * NS + s) * 3;
    const float qx = q[0], qy = q[1], qz = q[2];
    const float qsq = __fadd_rn(__fadd_rn(__fmul_rn(qx, qx), __fmul_rn(qy, qy)),
                                __fmul_rn(qz, qz));

    const float INF = __int_as_float(0x7f800000);
    float nd[NK]; int ni[NK];
#pragma unroll
    for (int t = 0; t < NK; t++) { nd[t] = INF; ni[t] = 0x7fffffff; }
    float wd = INF; int wslot = 0;

    float4 c = cand[0];
    for (int j = 0; j < NN; j++) {
        float4 nxt = cand[(j + 1) & (NN - 1)];   // prefetch next while computing
        float dot = __fadd_rn(__fadd_rn(__fmul_rn(qx, c.x), __fmul_rn(qy, c.y)),
                              __fmul_rn(qz, c.z));
        float sq = __fsub_rn(__fadd_rn(qsq, c.w), __fmul_rn(2.0f, dot));
        if (sq < wd) {   // strict: equal keeps earlier (lower) index, like top_k
#pragma unroll
            for (int t = 0; t < NK; t++)
                if (t == wslot) { nd[t] = sq; ni[t] = j; }
            float bw = nd[0]; int bwi = ni[0]; int bslot = 0;
#pragma unroll
            for (int t = 1; t < NK; t++) {
                bool g = (nd[t] > bw) || (nd[t] == bw && ni[t] > bwi);
                if (g) { bw = nd[t]; bwi = ni[t]; bslot = t; }
            }
            wd = bw; wslot = bslot;
        }
        c = nxt;
    }

    int* outp = g_idx + ((size_t)b * NS + s) * NK;
#pragma unroll
    for (int t = 0; t < NK; t++) outp[t] = ni[t];
}

// ---------------------------------------------------------------------------
// Stage 3: gather + 1x1 conv (67->128) + max over K + LayerNorm.
// smem-tiled GEMM: wt[67][128] transposed weights (float4, conflict-free),
// ft[67][40] transposed features (broadcast reads). Thread tile = 4 outch x
// 8 neighbors = 32 accumulators. No long-lived register arrays -> no spills.
// ---------------------------------------------------------------------------
#define FT_PITCH 40
#define QPB3 32
__global__ __launch_bounds__(128, 4)
void embed_kernel(const float* __restrict__ xyz, const float* __restrict__ voxels,
                  const float* __restrict__ w, const float* __restrict__ bias,
                  const float* __restrict__ gamma, const float* __restrict__ beta,
                  const float* __restrict__ new_xyz, float* __restrict__ out)
{
    __shared__ float wt[CIN * NOUT];        // [c][o]  34304 B
    __shared__ float ft[CIN * FT_PITCH];    // [c][k]  10720 B
    __shared__ float pm[4 * NOUT];          // [kg][o]  2048 B
    __shared__ float red[4];

    const int tid  = threadIdx.x;
    const int lane = tid & 31, wid = tid >> 5;
    const int og   = tid & 31;     // outch group: channels og*4..og*4+3
    const int kg   = tid >> 5;     // neighbor group: k = kg*8..kg*8+7
    const int k    = tid >> 2;     // gather: neighbor 0..31
    const int quad = tid & 3;      // gather: channel quarter

    // Transpose weights into smem once per block (thread = out channel).
    {
        const float* wrow = w + tid * CIN;
        for (int c = 0; c < CIN; c++)
            wt[c * NOUT + tid] = wrow[c];
    }
    float bs[4];
#pragma unroll
    for (int j = 0; j < 4; j++) bs[j] = bias[og * 4 + j];
    const float go = gamma[tid], be = beta[tid];

    for (int q = 0; q < QPB3; q++) {
        const int gq = blockIdx.x * QPB3 + q;
        const int b  = gq >> 10;

        __syncthreads();   // previous iteration's readers are done

        // ---- gather: feat transposed [channel][neighbor] ----
        const int nidx = g_idx[(size_t)gq * NK + k];
        const float4* vrow = (const float4*)(voxels + ((size_t)b * NN + nidx) * NC);
#pragma unroll
        for (int i = 0; i < 4; i++) {
            float4 v = vrow[quad * 4 + i];
            const int cb = 3 + quad * 16 + i * 4;
            ft[(cb + 0) * FT_PITCH + k] = v.x;
            ft[(cb + 1) * FT_PITCH + k] = v.y;
            ft[(cb + 2) * FT_PITCH + k] = v.z;
            ft[(cb + 3) * FT_PITCH + k] = v.w;
        }
        if (quad == 0) {
            const float* prow = xyz + ((size_t)b * NN + nidx) * 3;
            const float* qrow = new_xyz + (size_t)gq * 3;
            ft[0 * FT_PITCH + k] = __fsub_rn(prow[0], qrow[0]);
            ft[1 * FT_PITCH + k] = __fsub_rn(prow[1], qrow[1]);
            ft[2 * FT_PITCH + k] = __fsub_rn(prow[2], qrow[2]);
        }
        __syncthreads();

        // ---- GEMM: 4 outch x 8 neighbors per thread ----
        float a0[8], a1[8], a2[8], a3[8];
#pragma unroll
        for (int n = 0; n < 8; n++) { a0[n] = bs[0]; a1[n] = bs[1]; a2[n] = bs[2]; a3[n] = bs[3]; }

#pragma unroll 2
        for (int c = 0; c < CIN; c++) {
            float4 wv = *(const float4*)&wt[c * NOUT + og * 4];
            float4 f0 = *(const float4*)&ft[c * FT_PITCH + kg * 8];
            float4 f1 = *(const float4*)&ft[c * FT_PITCH + kg * 8 + 4];
            float fv[8] = {f0.x, f0.y, f0.z, f0.w, f1.x, f1.y, f1.z, f1.w};
#pragma unroll
            for (int n = 0; n < 8; n++) {
                a0[n] = fmaf(wv.x, fv[n], a0[n]);
                a1[n] = fmaf(wv.y, fv[n], a1[n]);
                a2[n] = fmaf(wv.z, fv[n], a2[n]);
                a3[n] = fmaf(wv.w, fv[n], a3[n]);
            }
        }

        // partial max over this thread's 8 neighbors
        float p0 = a0[0], p1 = a1[0], p2 = a2[0], p3 = a3[0];
#pragma unroll
        for (int n = 1; n < 8; n++) {
            p0 = fmaxf(p0, a0[n]); p1 = fmaxf(p1, a1[n]);
            p2 = fmaxf(p2, a2[n]); p3 = fmaxf(p3, a3[n]);
        }
        *(float4*)&pm[kg * NOUT + og * 4] = make_float4(p0, p1, p2, p3);
        __syncthreads();

        // ---- max across neighbor groups + LayerNorm (thread = out channel) ----
        float m = fmaxf(fmaxf(pm[0 * NOUT + tid], pm[1 * NOUT + tid]),
                        fmaxf(pm[2 * NOUT + tid], pm[3 * NOUT + tid]));

        float v = m;
#pragma unroll
        for (int off = 16; off; off >>= 1) v += __shfl_xor_sync(0xffffffffu, v, off);
        if (lane == 0) red[wid] = v;
        __syncthreads();
        const float mu = (red[0] + red[1] + red[2] + red[3]) * (1.0f / 128.0f);
        const float dm = m - mu;
        __syncthreads();
        float v2 = dm * dm;
#pragma unroll
        for (int off = 16; off; off >>= 1) v2 += __shfl_xor_sync(0xffffffffu, v2, off);
        if (lane == 0) red[wid] = v2;
        __syncthreads();
        const float var = (red[0] + red[1] + red[2] + red[3]) * (1.0f / 128.0f);
        out[(size_t)gq * NOUT + tid] = dm * rsqrtf(var + 1e-5f) * go + be;
    }
}

// ---------------------------------------------------------------------------
extern "C" void kernel_launch(void* const* d_in, const int* in_sizes, int n_in,
                              void* d_out, int out_size)
{
    const float* xyz    = (const float*)d_in[0];
    const float* voxels = (const float*)d_in[1];
    const float* conv_w = (const float*)d_in[2];
    const float* conv_b = (const float*)d_in[3];
    const float* ln_g   = (const float*)d_in[4];
    const float* ln_b   = (const float*)d_in[5];

    float* out      = (float*)d_out;                    // [B, S, OUT]
    float* new_xyz  = out + (size_t)NB * NS * NOUT;     // [B, S, 3]

    cudaFuncSetAttribute(fps_kernel, cudaFuncAttributeMaxDynamicSharedMemorySize,
                         3 * NN * sizeof(float));
    cudaFuncSetAttribute(knn_kernel, cudaFuncAttributeMaxDynamicSharedMemorySize,
                         NN * sizeof(float4));

    fps_kernel<<<NB, 1024, 3 * NN * sizeof(float)>>>(xyz, new_xyz);
    knn_kernel<<<NB * 8, 128, NN * sizeof(float4)>>>(xyz, new_xyz);
    embed_kernel<<<(NB * NS) / QPB3, 128>>>(xyz, voxels, conv_w, conv_b,
                                            ln_g, ln_b, new_xyz, out);
}

// round 7
// speedup vs baseline: 2.9944x; 1.7232x over previous
#include <cuda_runtime.h>
#include <cuda_bf16.h>
#include <cstdint>

#define NB   16
#define NN   4096
#define NS   1024
#define NK   32
#define NC   64
#define NOUT 128
#define CIN  67          // 3 + 64

// kNN index scratch (static device global; allocation is forbidden)
__device__ int g_idx[NB * NS * NK];

// ---------------------------------------------------------------------------
// Stage 1: farthest point sampling. One block per batch, 1024 threads,
// 4 points/thread register-resident. f32 REDUX max + exact-bit index match.
// (byte-identical to round 6: 509us measured)
// ---------------------------------------------------------------------------
__global__ __launch_bounds__(1024, 1)
void fps_kernel(const float* __restrict__ xyz, float* __restrict__ new_xyz)
{
    extern __shared__ float sm[];
    float* xs = sm;
    float* ys = sm + NN;
    float* zs = sm + 2 * NN;
    __shared__ unsigned int wmaxs[32];
    __shared__ int s_idx[2];

    const int b   = blockIdx.x;
    const int tid = threadIdx.x;
    const int lane = tid & 31, wid = tid >> 5;

    const float* gx = xyz + (size_t)b * NN * 3;
    for (int j = tid; j < NN * 3; j += 1024) {
        float v = gx[j];
        int p = j / 3, c = j - p * 3;
        if (c == 0) xs[p] = v; else if (c == 1) ys[p] = v; else zs[p] = v;
    }
    if (tid == 0) { s_idx[0] = 0x7fffffff; s_idx[1] = 0x7fffffff; }
    __syncthreads();

    const int base = tid * 4;
    float px[4], py[4], pz[4], dd[4];
#pragma unroll
    for (int j = 0; j < 4; j++) {
        px[j] = xs[base + j]; py[j] = ys[base + j]; pz[j] = zs[base + j];
        dd[j] = 1e10f;
    }

    int far = 0;
    for (int it = 0; it < NS; it++) {
        const float cx = xs[far], cy = ys[far], cz = zs[far];
        if (tid == 0) {
            float* o = new_xyz + ((size_t)b * NS + it) * 3;
            o[0] = cx; o[1] = cy; o[2] = cz;
        }
        float lm = 0.0f;   // distances are >= 0
#pragma unroll
        for (int j = 0; j < 4; j++) {
            float dx = __fsub_rn(px[j], cx);
            float dy = __fsub_rn(py[j], cy);
            float dz = __fsub_rn(pz[j], cz);
            float d  = __fadd_rn(__fadd_rn(__fmul_rn(dx, dx), __fmul_rn(dy, dy)),
                                 __fmul_rn(dz, dz));
            float nd = fminf(dd[j], d);
            dd[j] = nd;
            lm = fmaxf(lm, nd);
        }
        unsigned wm = __reduce_max_sync(0xffffffffu, __float_as_uint(lm));
        if (lane == 0) wmaxs[wid] = wm;
        __syncthreads();
        unsigned mv = __reduce_max_sync(0xffffffffu, wmaxs[lane]);
        const float mf = __uint_as_float(mv);
        int cand = 0x7fffffff;
#pragma unroll
        for (int j = 0; j < 4; j++)
            if (dd[j] == mf) cand = min(cand, base + j);
        if (cand != 0x7fffffff) atomicMin(&s_idx[it & 1], cand);
        if (tid == 0) s_idx[(it + 1) & 1] = 0x7fffffff;
        __syncthreads();
        far = s_idx[it & 1];
    }
}

// ---------------------------------------------------------------------------
// Stage 2: kNN. One thread per query; candidates (x,y,z,|p|^2) in smem.
// Top-32 kept as a binary MAX-heap of packed u64 keys (distbits<<32 | idx)
// in smem (stride-33 padding), root cached in a register. Replace-root +
// <=5-level sift-down (~40 instr) instead of predicated list + rescan (~200).
// Keys are unique -> exact 32 smallest under (dist, idx) = top_k tie rule.
// ---------------------------------------------------------------------------
#define HEAP_STRIDE 33
__global__ __launch_bounds__(128, 2)
void knn_kernel(const float* __restrict__ xyz, const float* __restrict__ new_xyz)
{
    extern __shared__ float4 cand[];                       // NN entries = 64 KB
    unsigned long long* heap =
        (unsigned long long*)(cand + NN);                  // 128*33*8 = 33.8 KB

    const int b     = blockIdx.x >> 3;         // 8 blocks of 128 queries per batch
    const int chunk = blockIdx.x & 7;
    const int tid   = threadIdx.x;

    const float* gx = xyz + (size_t)b * NN * 3;
    for (int p = tid; p < NN; p += 128) {
        float x = gx[p * 3], y = gx[p * 3 + 1], z = gx[p * 3 + 2];
        float psq = __fadd_rn(__fadd_rn(__fmul_rn(x, x), __fmul_rn(y, y)),
                              __fmul_rn(z, z));
        cand[p] = make_float4(x, y, z, psq);
    }

    unsigned long long* hp = heap + tid * HEAP_STRIDE;
#pragma unroll
    for (int t = 0; t < NK; t++) hp[t] = ~0ull;
    unsigned long long root = ~0ull;
    __syncthreads();

    const int s = chunk * 128 + tid;
    const float* q = new_xyz + ((size_t)b * NS + s) * 3;
    const float qx = q[0], qy = q[1], qz = q[2];
    const float qsq = __fadd_rn(__fadd_rn(__fmul_rn(qx, qx), __fmul_rn(qy, qy)),
                                __fmul_rn(qz, qz));

    float4 c = cand[0];
    for (int j = 0; j < NN; j++) {
        float4 nxt = cand[(j + 1) & (NN - 1)];   // prefetch next while computing
        float dot = __fadd_rn(__fadd_rn(__fmul_rn(qx, c.x), __fmul_rn(qy, c.y)),
                              __fmul_rn(qz, c.z));
        float sq = __fsub_rn(__fadd_rn(qsq, c.w), __fmul_rn(2.0f, dot));
        // order-preserving float -> uint map (handles tiny negatives exactly)
        unsigned ub = __float_as_uint(sq);
        ub ^= ((unsigned)((int)ub >> 31)) | 0x80000000u;
        unsigned long long key = ((unsigned long long)ub << 32) | (unsigned)j;

        if (key < root) {
            // replace root, sift down (max-heap over 32 nodes, <=5 levels)
            int pos = 0;
#pragma unroll
            for (int lvl = 0; lvl < 5; lvl++) {
                int ch = 2 * pos + 1;
                if (ch >= NK) break;
                unsigned long long lk = hp[ch];
                unsigned long long rk = (ch + 1 < NK) ? hp[ch + 1] : 0ull;
                unsigned long long mk = (rk > lk) ? rk : lk;
                int mc = (rk > lk) ? ch + 1 : ch;
                if (mk <= key) break;
                hp[pos] = mk;
                if (lvl == 0) root = mk;
                pos = mc;
            }
            hp[pos] = key;
            if (pos == 0) root = key;
        }
        c = nxt;
    }

    int* outp = g_idx + ((size_t)b * NS + s) * NK;
#pragma unroll
    for (int t = 0; t < NK; t++)
        outp[t] = (int)(hp[t] & 0xffffffffull);
}

// ---------------------------------------------------------------------------
// Stage 3: gather + 1x1 conv (67->128) + max over K + LayerNorm.
// (byte-identical to round 6)
// ---------------------------------------------------------------------------
#define FT_PITCH 40
#define QPB3 32
__global__ __launch_bounds__(128, 4)
void embed_kernel(const float* __restrict__ xyz, const float* __restrict__ voxels,
                  const float* __restrict__ w, const float* __restrict__ bias,
                  const float* __restrict__ gamma, const float* __restrict__ beta,
                  const float* __restrict__ new_xyz, float* __restrict__ out)
{
    __shared__ float wt[CIN * NOUT];        // [c][o]  34304 B
    __shared__ float ft[CIN * FT_PITCH];    // [c][k]  10720 B
    __shared__ float pm[4 * NOUT];          // [kg][o]  2048 B
    __shared__ float red[4];

    const int tid  = threadIdx.x;
    const int lane = tid & 31, wid = tid >> 5;
    const int og   = tid & 31;     // outch group: channels og*4..og*4+3
    const int kg   = tid >> 5;     // neighbor group: k = kg*8..kg*8+7
    const int k    = tid >> 2;     // gather: neighbor 0..31
    const int quad = tid & 3;      // gather: channel quarter

    {
        const float* wrow = w + tid * CIN;
        for (int c = 0; c < CIN; c++)
            wt[c * NOUT + tid] = wrow[c];
    }
    float bs[4];
#pragma unroll
    for (int j = 0; j < 4; j++) bs[j] = bias[og * 4 + j];
    const float go = gamma[tid], be = beta[tid];

    for (int q = 0; q < QPB3; q++) {
        const int gq = blockIdx.x * QPB3 + q;
        const int b  = gq >> 10;

        __syncthreads();   // previous iteration's readers are done

        const int nidx = g_idx[(size_t)gq * NK + k];
        const float4* vrow = (const float4*)(voxels + ((size_t)b * NN + nidx) * NC);
#pragma unroll
        for (int i = 0; i < 4; i++) {
            float4 v = vrow[quad * 4 + i];
            const int cb = 3 + quad * 16 + i * 4;
            ft[(cb + 0) * FT_PITCH + k] = v.x;
            ft[(cb + 1) * FT_PITCH + k] = v.y;
            ft[(cb + 2) * FT_PITCH + k] = v.z;
            ft[(cb + 3) * FT_PITCH + k] = v.w;
        }
        if (quad == 0) {
            const float* prow = xyz + ((size_t)b * NN + nidx) * 3;
            const float* qrow = new_xyz + (size_t)gq * 3;
            ft[0 * FT_PITCH + k] = __fsub_rn(prow[0], qrow[0]);
            ft[1 * FT_PITCH + k] = __fsub_rn(prow[1], qrow[1]);
            ft[2 * FT_PITCH + k] = __fsub_rn(prow[2], qrow[2]);
        }
        __syncthreads();

        float a0[8], a1[8], a2[8], a3[8];
#pragma unroll
        for (int n = 0; n < 8; n++) { a0[n] = bs[0]; a1[n] = bs[1]; a2[n] = bs[2]; a3[n] = bs[3]; }

#pragma unroll 2
        for (int c = 0; c < CIN; c++) {
            float4 wv = *(const float4*)&wt[c * NOUT + og * 4];
            float4 f0 = *(const float4*)&ft[c * FT_PITCH + kg * 8];
            float4 f1 = *(const float4*)&ft[c * FT_PITCH + kg * 8 + 4];
            float fv[8] = {f0.x, f0.y, f0.z, f0.w, f1.x, f1.y, f1.z, f1.w};
#pragma unroll
            for (int n = 0; n < 8; n++) {
                a0[n] = fmaf(wv.x, fv[n], a0[n]);
                a1[n] = fmaf(wv.y, fv[n], a1[n]);
                a2[n] = fmaf(wv.z, fv[n], a2[n]);
                a3[n] = fmaf(wv.w, fv[n], a3[n]);
            }
        }

        float p0 = a0[0], p1 = a1[0], p2 = a2[0], p3 = a3[0];
#pragma unroll
        for (int n = 1; n < 8; n++) {
            p0 = fmaxf(p0, a0[n]); p1 = fmaxf(p1, a1[n]);
            p2 = fmaxf(p2, a2[n]); p3 = fmaxf(p3, a3[n]);
        }
        *(float4*)&pm[kg * NOUT + og * 4] = make_float4(p0, p1, p2, p3);
        __syncthreads();

        float m = fmaxf(fmaxf(pm[0 * NOUT + tid], pm[1 * NOUT + tid]),
                        fmaxf(pm[2 * NOUT + tid], pm[3 * NOUT + tid]));

        float v = m;
#pragma unroll
        for (int off = 16; off; off >>= 1) v += __shfl_xor_sync(0xffffffffu, v, off);
        if (lane == 0) red[wid] = v;
        __syncthreads();
        const float mu = (red[0] + red[1] + red[2] + red[3]) * (1.0f / 128.0f);
        const float dm = m - mu;
        __syncthreads();
        float v2 = dm * dm;
#pragma unroll
        for (int off = 16; off; off >>= 1) v2 += __shfl_xor_sync(0xffffffffu, v2, off);
        if (lane == 0) red[wid] = v2;
        __syncthreads();
        const float var = (red[0] + red[1] + red[2] + red[3]) * (1.0f / 128.0f);
        out[(size_t)gq * NOUT + tid] = dm * rsqrtf(var + 1e-5f) * go + be;
    }
}

// ---------------------------------------------------------------------------
extern "C" void kernel_launch(void* const* d_in, const int* in_sizes, int n_in,
                              void* d_out, int out_size)
{
    const float* xyz    = (const float*)d_in[0];
    const float* voxels = (const float*)d_in[1];
    const float* conv_w = (const float*)d_in[2];
    const float* conv_b = (const float*)d_in[3];
    const float* ln_g   = (const float*)d_in[4];
    const float* ln_b   = (const float*)d_in[5];

    float* out      = (float*)d_out;                    // [B, S, OUT]
    float* new_xyz  = out + (size_t)NB * NS * NOUT;     // [B, S, 3]

    const size_t knn_smem = NN * sizeof(float4)
                          + 128 * HEAP_STRIDE * sizeof(unsigned long long);

    cudaFuncSetAttribute(fps_kernel, cudaFuncAttributeMaxDynamicSharedMemorySize,
                         3 * NN * sizeof(float));
    cudaFuncSetAttribute(knn_kernel, cudaFuncAttributeMaxDynamicSharedMemorySize,
                         (int)knn_smem);

    fps_kernel<<<NB, 1024, 3 * NN * sizeof(float)>>>(xyz, new_xyz);
    knn_kernel<<<NB * 8, 128, knn_smem>>>(xyz, new_xyz);
    embed_kernel<<<(NB * NS) / QPB3, 128>>>(xyz, voxels, conv_w, conv_b,
                                            ln_g, ln_b, new_xyz, out);
}

// round 8
// speedup vs baseline: 3.2316x; 1.0792x over previous
#include <cuda_runtime.h>
#include <cuda_bf16.h>
#include <cstdint>

#define NB   16
#define NN   4096
#define NS   1024
#define NK   32
#define NC   64
#define NOUT 128
#define CIN  67          // 3 + 64

// kNN index scratch (static device global; allocation is forbidden)
__device__ int g_idx[NB * NS * NK];

// ---- packed f32x2 helpers (SIMD f32, .rn rounding == scalar f32 exactly) ----
__device__ __forceinline__ unsigned long long pk2(float lo, float hi) {
    unsigned long long r;
    asm("mov.b64 %0, {%1, %2};" : "=l"(r)
        : "r"(__float_as_uint(lo)), "r"(__float_as_uint(hi)));
    return r;
}
__device__ __forceinline__ void upk2(unsigned long long v, float& lo, float& hi) {
    unsigned a, b;
    asm("mov.b64 {%0, %1}, %2;" : "=r"(a), "=r"(b) : "l"(v));
    lo = __uint_as_float(a); hi = __uint_as_float(b);
}
#define F2ADD(o, a, b) asm("add.rn.f32x2 %0, %1, %2;" : "=l"(o) : "l"(a), "l"(b))
#define F2MUL(o, a, b) asm("mul.rn.f32x2 %0, %1, %2;" : "=l"(o) : "l"(a), "l"(b))
#define F2FMA(o, a, b, c) asm("fma.rn.f32x2 %0, %1, %2, %3;" : "=l"(o) : "l"(a), "l"(b), "l"(c))

// ---------------------------------------------------------------------------
// Stage 1: FPS. 512 threads, 8 points/thread, ONE barrier per iteration.
// Warp stage: REDUX max(dist bits) + REDUX min(idx) -> packed u64 pair.
// Block stage: all warps redundantly reduce 16 pairs via two more REDUXes.
// pairs[] double-buffered by iteration parity (WAR-safe with a single bar).
// Distance math packed f32x2 (rounding identical to scalar f32).
// ---------------------------------------------------------------------------
__global__ __launch_bounds__(512, 1)
void fps_kernel(const float* __restrict__ xyz, float* __restrict__ new_xyz)
{
    extern __shared__ float sm[];
    float* xs = sm;
    float* ys = sm + NN;
    float* zs = sm + 2 * NN;
    __shared__ unsigned long long pairs[2][16];

    const int b   = blockIdx.x;
    const int tid = threadIdx.x;
    const int lane = tid & 31, wid = tid >> 5;

    const float* gx = xyz + (size_t)b * NN * 3;
    for (int j = tid; j < NN * 3; j += 512) {
        float v = gx[j];
        int p = j / 3, c = j - p * 3;
        if (c == 0) xs[p] = v; else if (c == 1) ys[p] = v; else zs[p] = v;
    }
    __syncthreads();

    const int base = tid * 8;
    unsigned long long pxx[4], pyy[4], pzz[4];
    float dd[8];
#pragma unroll
    for (int p = 0; p < 4; p++) {
        pxx[p] = pk2(xs[base + 2 * p], xs[base + 2 * p + 1]);
        pyy[p] = pk2(ys[base + 2 * p], ys[base + 2 * p + 1]);
        pzz[p] = pk2(zs[base + 2 * p], zs[base + 2 * p + 1]);
        dd[2 * p] = 1e10f; dd[2 * p + 1] = 1e10f;
    }

    int far = 0;
    for (int it = 0; it < NS; it++) {
        const float cx = xs[far], cy = ys[far], cz = zs[far];
        if (tid == 0) {
            float* o = new_xyz + ((size_t)b * NS + it) * 3;
            o[0] = cx; o[1] = cy; o[2] = cz;
        }
        // (p - c) computed as p + (-c): negation is exact, add.rn == sub.rn
        const unsigned long long ncx = pk2(-cx, -cx);
        const unsigned long long ncy = pk2(-cy, -cy);
        const unsigned long long ncz = pk2(-cz, -cz);

        float lm = 0.0f;   // distances are >= 0
        int lidx = 0;
#pragma unroll
        for (int p = 0; p < 4; p++) {
            unsigned long long dx, dy, dz, t;
            F2ADD(dx, pxx[p], ncx);
            F2ADD(dy, pyy[p], ncy);
            F2ADD(dz, pzz[p], ncz);
            F2MUL(t, dx, dx);
            F2FMA(t, dy, dy, t);
            F2FMA(t, dz, dz, t);
            float d0, d1; upk2(t, d0, d1);
            float n0 = fminf(dd[2 * p], d0);
            float n1 = fminf(dd[2 * p + 1], d1);
            dd[2 * p] = n0; dd[2 * p + 1] = n1;
            if (n0 > lm) { lm = n0; lidx = base + 2 * p; }       // strict >:
            if (n1 > lm) { lm = n1; lidx = base + 2 * p + 1; }   // lowest idx wins
        }
        // warp reduce: max dist, then min idx among lanes holding that max
        const unsigned lmb = __float_as_uint(lm);
        const unsigned wm  = __reduce_max_sync(0xffffffffu, lmb);
        const unsigned wix = __reduce_min_sync(0xffffffffu,
                                (lmb == wm) ? (unsigned)lidx : 0xffffffffu);
        if (lane == 0)
            pairs[it & 1][wid] = ((unsigned long long)wm << 32) | (4095u - wix);
        __syncthreads();
        // block reduce (all warps redundantly): max hi, then max lo among hi-matches
        const unsigned long long kk = (lane < 16) ? pairs[it & 1][lane] : 0ull;
        const unsigned hi = (unsigned)(kk >> 32);
        const unsigned mh = __reduce_max_sync(0xffffffffu, hi);
        const unsigned lo = (hi == mh) ? (unsigned)kk : 0u;
        const unsigned ml = __reduce_max_sync(0xffffffffu, lo);  // max(4095-idx) = min idx
        far = 4095 - (int)ml;
    }
}

// ---------------------------------------------------------------------------
// Stage 2: kNN. Algorithm identical to round 7 (register-rooted smem max-heap),
// but 256 threads/block, 64 blocks -> 2 warps/SMSP (halves exposed sift chains).
// ---------------------------------------------------------------------------
#define HEAP_STRIDE 33
__global__ __launch_bounds__(256, 1)
void knn_kernel(const float* __restrict__ xyz, const float* __restrict__ new_xyz)
{
    extern __shared__ float4 cand[];                       // NN entries = 64 KB
    unsigned long long* heap =
        (unsigned long long*)(cand + NN);                  // 256*33*8 = 67.5 KB

    const int b     = blockIdx.x >> 2;         // 4 blocks of 256 queries per batch
    const int chunk = blockIdx.x & 3;
    const int tid   = threadIdx.x;

    const float* gx = xyz + (size_t)b * NN * 3;
    for (int p = tid; p < NN; p += 256) {
        float x = gx[p * 3], y = gx[p * 3 + 1], z = gx[p * 3 + 2];
        float psq = __fadd_rn(__fadd_rn(__fmul_rn(x, x), __fmul_rn(y, y)),
                              __fmul_rn(z, z));
        cand[p] = make_float4(x, y, z, psq);
    }

    unsigned long long* hp = heap + tid * HEAP_STRIDE;
#pragma unroll
    for (int t = 0; t < NK; t++) hp[t] = ~0ull;
    unsigned long long root = ~0ull;
    __syncthreads();

    const int s = chunk * 256 + tid;
    const float* q = new_xyz + ((size_t)b * NS + s) * 3;
    const float qx = q[0], qy = q[1], qz = q[2];
    const float qsq = __fadd_rn(__fadd_rn(__fmul_rn(qx, qx), __fmul_rn(qy, qy)),
                                __fmul_rn(qz, qz));

    float4 c = cand[0];
    for (int j = 0; j < NN; j++) {
        float4 nxt = cand[(j + 1) & (NN - 1)];   // prefetch next while computing
        float dot = __fadd_rn(__fadd_rn(__fmul_rn(qx, c.x), __fmul_rn(qy, c.y)),
                              __fmul_rn(qz, c.z));
        float sq = __fsub_rn(__fadd_rn(qsq, c.w), __fmul_rn(2.0f, dot));
        unsigned ub = __float_as_uint(sq);
        ub ^= ((unsigned)((int)ub >> 31)) | 0x80000000u;   // order-preserving map
        unsigned long long key = ((unsigned long long)ub << 32) | (unsigned)j;

        if (key < root) {
            int pos = 0;
#pragma unroll
            for (int lvl = 0; lvl < 5; lvl++) {
                int ch = 2 * pos + 1;
                if (ch >= NK) break;
                unsigned long long lk = hp[ch];
                unsigned long long rk = (ch + 1 < NK) ? hp[ch + 1] : 0ull;
                unsigned long long mk = (rk > lk) ? rk : lk;
                int mc = (rk > lk) ? ch + 1 : ch;
                if (mk <= key) break;
                hp[pos] = mk;
                if (lvl == 0) root = mk;
                pos = mc;
            }
            hp[pos] = key;
            if (pos == 0) root = key;
        }
        c = nxt;
    }

    int* outp = g_idx + ((size_t)b * NS + s) * NK;
#pragma unroll
    for (int t = 0; t < NK; t++)
        outp[t] = (int)(hp[t] & 0xffffffffull);
}

// ---------------------------------------------------------------------------
// Stage 3: gather + 1x1 conv (67->128) + max over K + LayerNorm.
// (byte-identical to rounds 6/7)
// ---------------------------------------------------------------------------
#define FT_PITCH 40
#define QPB3 32
__global__ __launch_bounds__(128, 4)
void embed_kernel(const float* __restrict__ xyz, const float* __restrict__ voxels,
                  const float* __restrict__ w, const float* __restrict__ bias,
                  const float* __restrict__ gamma, const float* __restrict__ beta,
                  const float* __restrict__ new_xyz, float* __restrict__ out)
{
    __shared__ float wt[CIN * NOUT];        // [c][o]  34304 B
    __shared__ float ft[CIN * FT_PITCH];    // [c][k]  10720 B
    __shared__ float pm[4 * NOUT];          // [kg][o]  2048 B
    __shared__ float red[4];

    const int tid  = threadIdx.x;
    const int lane = tid & 31, wid = tid >> 5;
    const int og   = tid & 31;     // outch group: channels og*4..og*4+3
    const int kg   = tid >> 5;     // neighbor group: k = kg*8..kg*8+7
    const int k    = tid >> 2;     // gather: neighbor 0..31
    const int quad = tid & 3;      // gather: channel quarter

    {
        const float* wrow = w + tid * CIN;
        for (int c = 0; c < CIN; c++)
            wt[c * NOUT + tid] = wrow[c];
    }
    float bs[4];
#pragma unroll
    for (int j = 0; j < 4; j++) bs[j] = bias[og * 4 + j];
    const float go = gamma[tid], be = beta[tid];

    for (int q = 0; q < QPB3; q++) {
        const int gq = blockIdx.x * QPB3 + q;
        const int b  = gq >> 10;

        __syncthreads();   // previous iteration's readers are done

        const int nidx = g_idx[(size_t)gq * NK + k];
        const float4* vrow = (const float4*)(voxels + ((size_t)b * NN + nidx) * NC);
#pragma unroll
        for (int i = 0; i < 4; i++) {
            float4 v = vrow[quad * 4 + i];
            const int cb = 3 + quad * 16 + i * 4;
            ft[(cb + 0) * FT_PITCH + k] = v.x;
            ft[(cb + 1) * FT_PITCH + k] = v.y;
            ft[(cb + 2) * FT_PITCH + k] = v.z;
            ft[(cb + 3) * FT_PITCH + k] = v.w;
        }
        if (quad == 0) {
            const float* prow = xyz + ((size_t)b * NN + nidx) * 3;
            const float* qrow = new_xyz + (size_t)gq * 3;
            ft[0 * FT_PITCH + k] = __fsub_rn(prow[0], qrow[0]);
            ft[1 * FT_PITCH + k] = __fsub_rn(prow[1], qrow[1]);
            ft[2 * FT_PITCH + k] = __fsub_rn(prow[2], qrow[2]);
        }
        __syncthreads();

        float a0[8], a1[8], a2[8], a3[8];
#pragma unroll
        for (int n = 0; n < 8; n++) { a0[n] = bs[0]; a1[n] = bs[1]; a2[n] = bs[2]; a3[n] = bs[3]; }

#pragma unroll 2
        for (int c = 0; c < CIN; c++) {
            float4 wv = *(const float4*)&wt[c * NOUT + og * 4];
            float4 f0 = *(const float4*)&ft[c * FT_PITCH + kg * 8];
            float4 f1 = *(const float4*)&ft[c * FT_PITCH + kg * 8 + 4];
            float fv[8] = {f0.x, f0.y, f0.z, f0.w, f1.x, f1.y, f1.z, f1.w};
#pragma unroll
            for (int n = 0; n < 8; n++) {
                a0[n] = fmaf(wv.x, fv[n], a0[n]);
                a1[n] = fmaf(wv.y, fv[n], a1[n]);
                a2[n] = fmaf(wv.z, fv[n], a2[n]);
                a3[n] = fmaf(wv.w, fv[n], a3[n]);
            }
        }

        float p0 = a0[0], p1 = a1[0], p2 = a2[0], p3 = a3[0];
#pragma unroll
        for (int n = 1; n < 8; n++) {
            p0 = fmaxf(p0, a0[n]); p1 = fmaxf(p1, a1[n]);
            p2 = fmaxf(p2, a2[n]); p3 = fmaxf(p3, a3[n]);
        }
        *(float4*)&pm[kg * NOUT + og * 4] = make_float4(p0, p1, p2, p3);
        __syncthreads();

        float m = fmaxf(fmaxf(pm[0 * NOUT + tid], pm[1 * NOUT + tid]),
                        fmaxf(pm[2 * NOUT + tid], pm[3 * NOUT + tid]));

        float v = m;
#pragma unroll
        for (int off = 16; off; off >>= 1) v += __shfl_xor_sync(0xffffffffu, v, off);
        if (lane == 0) red[wid] = v;
        __syncthreads();
        const float mu = (red[0] + red[1] + red[2] + red[3]) * (1.0f / 128.0f);
        const float dm = m - mu;
        __syncthreads();
        float v2 = dm * dm;
#pragma unroll
        for (int off = 16; off; off >>= 1) v2 += __shfl_xor_sync(0xffffffffu, v2, off);
        if (lane == 0) red[wid] = v2;
        __syncthreads();
        const float var = (red[0] + red[1] + red[2] + red[3]) * (1.0f / 128.0f);
        out[(size_t)gq * NOUT + tid] = dm * rsqrtf(var + 1e-5f) * go + be;
    }
}

// ---------------------------------------------------------------------------
extern "C" void kernel_launch(void* const* d_in, const int* in_sizes, int n_in,
                              void* d_out, int out_size)
{
    const float* xyz    = (const float*)d_in[0];
    const float* voxels = (const float*)d_in[1];
    const float* conv_w = (const float*)d_in[2];
    const float* conv_b = (const float*)d_in[3];
    const float* ln_g   = (const float*)d_in[4];
    const float* ln_b   = (const float*)d_in[5];

    float* out      = (float*)d_out;                    // [B, S, OUT]
    float* new_xyz  = out + (size_t)NB * NS * NOUT;     // [B, S, 3]

    const size_t knn_smem = NN * sizeof(float4)
                          + 256 * HEAP_STRIDE * sizeof(unsigned long long);

    cudaFuncSetAttribute(fps_kernel, cudaFuncAttributeMaxDynamicSharedMemorySize,
                         3 * NN * sizeof(float));
    cudaFuncSetAttribute(knn_kernel, cudaFuncAttributeMaxDynamicSharedMemorySize,
                         (int)knn_smem);

    fps_kernel<<<NB, 512, 3 * NN * sizeof(float)>>>(xyz, new_xyz);
    knn_kernel<<<NB * 4, 256, knn_smem>>>(xyz, new_xyz);
    embed_kernel<<<(NB * NS) / QPB3, 128>>>(xyz, voxels, conv_w, conv_b,
                                            ln_g, ln_b, new_xyz, out);
}

// round 9
// speedup vs baseline: 3.8748x; 1.1991x over previous
#include <cuda_runtime.h>
#include <cuda_bf16.h>
#include <cstdint>

#define NB   16
#define NN   4096
#define NS   1024
#define NK   32
#define NC   64
#define NOUT 128
#define CIN  67          // 3 + 64

// kNN index scratch (static device global; allocation is forbidden)
__device__ int g_idx[NB * NS * NK];

// ---- packed f32x2 helpers (SIMD f32, .rn rounding == scalar f32 exactly) ----
__device__ __forceinline__ unsigned long long pk2(float lo, float hi) {
    unsigned long long r;
    asm("mov.b64 %0, {%1, %2};" : "=l"(r)
        : "r"(__float_as_uint(lo)), "r"(__float_as_uint(hi)));
    return r;
}
__device__ __forceinline__ void upk2(unsigned long long v, float& lo, float& hi) {
    unsigned a, b;
    asm("mov.b64 {%0, %1}, %2;" : "=r"(a), "=r"(b) : "l"(v));
    lo = __uint_as_float(a); hi = __uint_as_float(b);
}
#define F2ADD(o, a, b) asm("add.rn.f32x2 %0, %1, %2;" : "=l"(o) : "l"(a), "l"(b))
#define F2MUL(o, a, b) asm("mul.rn.f32x2 %0, %1, %2;" : "=l"(o) : "l"(a), "l"(b))
#define F2FMA(o, a, b, c) asm("fma.rn.f32x2 %0, %1, %2, %3;" : "=l"(o) : "l"(a), "l"(b), "l"(c))

// ---------------------------------------------------------------------------
// Stage 1: FPS. (byte-identical to round 8: 356us measured)
// ---------------------------------------------------------------------------
__global__ __launch_bounds__(512, 1)
void fps_kernel(const float* __restrict__ xyz, float* __restrict__ new_xyz)
{
    extern __shared__ float sm[];
    float* xs = sm;
    float* ys = sm + NN;
    float* zs = sm + 2 * NN;
    __shared__ unsigned long long pairs[2][16];

    const int b   = blockIdx.x;
    const int tid = threadIdx.x;
    const int lane = tid & 31, wid = tid >> 5;

    const float* gx = xyz + (size_t)b * NN * 3;
    for (int j = tid; j < NN * 3; j += 512) {
        float v = gx[j];
        int p = j / 3, c = j - p * 3;
        if (c == 0) xs[p] = v; else if (c == 1) ys[p] = v; else zs[p] = v;
    }
    __syncthreads();

    const int base = tid * 8;
    unsigned long long pxx[4], pyy[4], pzz[4];
    float dd[8];
#pragma unroll
    for (int p = 0; p < 4; p++) {
        pxx[p] = pk2(xs[base + 2 * p], xs[base + 2 * p + 1]);
        pyy[p] = pk2(ys[base + 2 * p], ys[base + 2 * p + 1]);
        pzz[p] = pk2(zs[base + 2 * p], zs[base + 2 * p + 1]);
        dd[2 * p] = 1e10f; dd[2 * p + 1] = 1e10f;
    }

    int far = 0;
    for (int it = 0; it < NS; it++) {
        const float cx = xs[far], cy = ys[far], cz = zs[far];
        if (tid == 0) {
            float* o = new_xyz + ((size_t)b * NS + it) * 3;
            o[0] = cx; o[1] = cy; o[2] = cz;
        }
        const unsigned long long ncx = pk2(-cx, -cx);
        const unsigned long long ncy = pk2(-cy, -cy);
        const unsigned long long ncz = pk2(-cz, -cz);

        float lm = 0.0f;
        int lidx = 0;
#pragma unroll
        for (int p = 0; p < 4; p++) {
            unsigned long long dx, dy, dz, t;
            F2ADD(dx, pxx[p], ncx);
            F2ADD(dy, pyy[p], ncy);
            F2ADD(dz, pzz[p], ncz);
            F2MUL(t, dx, dx);
            F2FMA(t, dy, dy, t);
            F2FMA(t, dz, dz, t);
            float d0, d1; upk2(t, d0, d1);
            float n0 = fminf(dd[2 * p], d0);
            float n1 = fminf(dd[2 * p + 1], d1);
            dd[2 * p] = n0; dd[2 * p + 1] = n1;
            if (n0 > lm) { lm = n0; lidx = base + 2 * p; }
            if (n1 > lm) { lm = n1; lidx = base + 2 * p + 1; }
        }
        const unsigned lmb = __float_as_uint(lm);
        const unsigned wm  = __reduce_max_sync(0xffffffffu, lmb);
        const unsigned wix = __reduce_min_sync(0xffffffffu,
                                (lmb == wm) ? (unsigned)lidx : 0xffffffffu);
        if (lane == 0)
            pairs[it & 1][wid] = ((unsigned long long)wm << 32) | (4095u - wix);
        __syncthreads();
        const unsigned long long kk = (lane < 16) ? pairs[it & 1][lane] : 0ull;
        const unsigned hi = (unsigned)(kk >> 32);
        const unsigned mh = __reduce_max_sync(0xffffffffu, hi);
        const unsigned lo = (hi == mh) ? (unsigned)kk : 0u;
        const unsigned ml = __reduce_max_sync(0xffffffffu, lo);
        far = 4095 - (int)ml;
    }
}

// ---------------------------------------------------------------------------
// Stage 2: kNN, split-scan. 2 threads per query, each scans a disjoint half
// (2048 candidates) into its own 32-key max-heap (u64 keys unique: mapped
// distbits<<32 | global idx). Then exact rank-merge: each key's rank among
// the 64 union keys; rank<32 -> g_idx slot=rank. Top-32 of union of per-half
// top-32s == exact top-32 (tie rule = key order = (dist, idx), like top_k).
// 256 thr/block = 128 queries; 128 blocks -> 128 SMs.
// ---------------------------------------------------------------------------
#define HEAP_STRIDE 33
#define HALF 2048
__global__ __launch_bounds__(256, 1)
void knn_kernel(const float* __restrict__ xyz, const float* __restrict__ new_xyz)
{
    extern __shared__ float4 cand[];                       // NN entries = 64 KB
    unsigned long long* heap =
        (unsigned long long*)(cand + NN);                  // 256*33*8 = 67.6 KB

    const int b     = blockIdx.x >> 3;         // 8 blocks of 128 queries per batch
    const int chunk = blockIdx.x & 7;
    const int tid   = threadIdx.x;
    const int qloc  = tid & 127;               // query within chunk
    const int half  = tid >> 7;                // candidate half 0/1

    const float* gx = xyz + (size_t)b * NN * 3;
    for (int p = tid; p < NN; p += 256) {
        float x = gx[p * 3], y = gx[p * 3 + 1], z = gx[p * 3 + 2];
        float psq = __fadd_rn(__fadd_rn(__fmul_rn(x, x), __fmul_rn(y, y)),
                              __fmul_rn(z, z));
        cand[p] = make_float4(x, y, z, psq);
    }

    unsigned long long* hp = heap + tid * HEAP_STRIDE;
#pragma unroll
    for (int t = 0; t < NK; t++) hp[t] = ~0ull;
    unsigned long long root = ~0ull;
    __syncthreads();

    const int s = chunk * 128 + qloc;
    const float* q = new_xyz + ((size_t)b * NS + s) * 3;
    const float qx = q[0], qy = q[1], qz = q[2];
    const float qsq = __fadd_rn(__fadd_rn(__fmul_rn(qx, qx), __fmul_rn(qy, qy)),
                                __fmul_rn(qz, qz));

    const int start = half * HALF;
    float4 c = cand[start];
    for (int i = 0; i < HALF; i++) {
        float4 nxt = cand[start + ((i + 1) & (HALF - 1))];   // prefetch
        const int j = start + i;
        float dot = __fadd_rn(__fadd_rn(__fmul_rn(qx, c.x), __fmul_rn(qy, c.y)),
                              __fmul_rn(qz, c.z));
        float sq = __fsub_rn(__fadd_rn(qsq, c.w), __fmul_rn(2.0f, dot));
        unsigned ub = __float_as_uint(sq);
        ub ^= ((unsigned)((int)ub >> 31)) | 0x80000000u;   // order-preserving map
        unsigned long long key = ((unsigned long long)ub << 32) | (unsigned)j;

        if (key < root) {
            int pos = 0;
#pragma unroll
            for (int lvl = 0; lvl < 5; lvl++) {
                int ch = 2 * pos + 1;
                if (ch >= NK) break;
                unsigned long long lk = hp[ch];
                unsigned long long rk = (ch + 1 < NK) ? hp[ch + 1] : 0ull;
                unsigned long long mk = (rk > lk) ? rk : lk;
                int mc = (rk > lk) ? ch + 1 : ch;
                if (mk <= key) break;
                hp[pos] = mk;
                if (lvl == 0) root = mk;
                pos = mc;
            }
            hp[pos] = key;
            if (pos == 0) root = key;
        }
        c = nxt;
    }
    __syncthreads();

    // rank merge: my 32 keys vs partner's 32; unique keys -> ranks 0..63.
    const unsigned long long* hq = heap + (tid ^ 128) * HEAP_STRIDE;
    int* outp = g_idx + ((size_t)b * NS + s) * NK;
#pragma unroll 4
    for (int i = 0; i < NK; i++) {
        const unsigned long long k = hp[i];
        int r = 0;
#pragma unroll 8
        for (int t = 0; t < NK; t++) r += (hp[t] < k);
#pragma unroll 8
        for (int t = 0; t < NK; t++) r += (hq[t] < k);
        if (r < NK) outp[r] = (int)(k & 0xffffffffull);
    }
}

// ---------------------------------------------------------------------------
// Stage 3: gather + 1x1 conv (67->128) + max over K + LayerNorm.
// (byte-identical to rounds 6/7/8)
// ---------------------------------------------------------------------------
#define FT_PITCH 40
#define QPB3 32
__global__ __launch_bounds__(128, 4)
void embed_kernel(const float* __restrict__ xyz, const float* __restrict__ voxels,
                  const float* __restrict__ w, const float* __restrict__ bias,
                  const float* __restrict__ gamma, const float* __restrict__ beta,
                  const float* __restrict__ new_xyz, float* __restrict__ out)
{
    __shared__ float wt[CIN * NOUT];        // [c][o]  34304 B
    __shared__ float ft[CIN * FT_PITCH];    // [c][k]  10720 B
    __shared__ float pm[4 * NOUT];          // [kg][o]  2048 B
    __shared__ float red[4];

    const int tid  = threadIdx.x;
    const int lane = tid & 31, wid = tid >> 5;
    const int og   = tid & 31;
    const int kg   = tid >> 5;
    const int k    = tid >> 2;
    const int quad = tid & 3;

    {
        const float* wrow = w + tid * CIN;
        for (int c = 0; c < CIN; c++)
            wt[c * NOUT + tid] = wrow[c];
    }
    float bs[4];
#pragma unroll
    for (int j = 0; j < 4; j++) bs[j] = bias[og * 4 + j];
    const float go = gamma[tid], be = beta[tid];

    for (int q = 0; q < QPB3; q++) {
        const int gq = blockIdx.x * QPB3 + q;
        const int b  = gq >> 10;

        __syncthreads();

        const int nidx = g_idx[(size_t)gq * NK + k];
        const float4* vrow = (const float4*)(voxels + ((size_t)b * NN + nidx) * NC);
#pragma unroll
        for (int i = 0; i < 4; i++) {
            float4 v = vrow[quad * 4 + i];
            const int cb = 3 + quad * 16 + i * 4;
            ft[(cb + 0) * FT_PITCH + k] = v.x;
            ft[(cb + 1) * FT_PITCH + k] = v.y;
            ft[(cb + 2) * FT_PITCH + k] = v.z;
            ft[(cb + 3) * FT_PITCH + k] = v.w;
        }
        if (quad == 0) {
            const float* prow = xyz + ((size_t)b * NN + nidx) * 3;
            const float* qrow = new_xyz + (size_t)gq * 3;
            ft[0 * FT_PITCH + k] = __fsub_rn(prow[0], qrow[0]);
            ft[1 * FT_PITCH + k] = __fsub_rn(prow[1], qrow[1]);
            ft[2 * FT_PITCH + k] = __fsub_rn(prow[2], qrow[2]);
        }
        __syncthreads();

        float a0[8], a1[8], a2[8], a3[8];
#pragma unroll
        for (int n = 0; n < 8; n++) { a0[n] = bs[0]; a1[n] = bs[1]; a2[n] = bs[2]; a3[n] = bs[3]; }

#pragma unroll 2
        for (int c = 0; c < CIN; c++) {
            float4 wv = *(const float4*)&wt[c * NOUT + og * 4];
            float4 f0 = *(const float4*)&ft[c * FT_PITCH + kg * 8];
            float4 f1 = *(const float4*)&ft[c * FT_PITCH + kg * 8 + 4];
            float fv[8] = {f0.x, f0.y, f0.z, f0.w, f1.x, f1.y, f1.z, f1.w};
#pragma unroll
            for (int n = 0; n < 8; n++) {
                a0[n] = fmaf(wv.x, fv[n], a0[n]);
                a1[n] = fmaf(wv.y, fv[n], a1[n]);
                a2[n] = fmaf(wv.z, fv[n], a2[n]);
                a3[n] = fmaf(wv.w, fv[n], a3[n]);
            }
        }

        float p0 = a0[0], p1 = a1[0], p2 = a2[0], p3 = a3[0];
#pragma unroll
        for (int n = 1; n < 8; n++) {
            p0 = fmaxf(p0, a0[n]); p1 = fmaxf(p1, a1[n]);
            p2 = fmaxf(p2, a2[n]); p3 = fmaxf(p3, a3[n]);
        }
        *(float4*)&pm[kg * NOUT + og * 4] = make_float4(p0, p1, p2, p3);
        __syncthreads();

        float m = fmaxf(fmaxf(pm[0 * NOUT + tid], pm[1 * NOUT + tid]),
                        fmaxf(pm[2 * NOUT + tid], pm[3 * NOUT + tid]));

        float v = m;
#pragma unroll
        for (int off = 16; off; off >>= 1) v += __shfl_xor_sync(0xffffffffu, v, off);
        if (lane == 0) red[wid] = v;
        __syncthreads();
        const float mu = (red[0] + red[1] + red[2] + red[3]) * (1.0f / 128.0f);
        const float dm = m - mu;
        __syncthreads();
        float v2 = dm * dm;
#pragma unroll
        for (int off = 16; off; off >>= 1) v2 += __shfl_xor_sync(0xffffffffu, v2, off);
        if (lane == 0) red[wid] = v2;
        __syncthreads();
        const float var = (red[0] + red[1] + red[2] + red[3]) * (1.0f / 128.0f);
        out[(size_t)gq * NOUT + tid] = dm * rsqrtf(var + 1e-5f) * go + be;
    }
}

// ---------------------------------------------------------------------------
extern "C" void kernel_launch(void* const* d_in, const int* in_sizes, int n_in,
                              void* d_out, int out_size)
{
    const float* xyz    = (const float*)d_in[0];
    const float* voxels = (const float*)d_in[1];
    const float* conv_w = (const float*)d_in[2];
    const float* conv_b = (const float*)d_in[3];
    const float* ln_g   = (const float*)d_in[4];
    const float* ln_b   = (const float*)d_in[5];

    float* out      = (float*)d_out;                    // [B, S, OUT]
    float* new_xyz  = out + (size_t)NB * NS * NOUT;     // [B, S, 3]

    const size_t knn_smem = NN * sizeof(float4)
                          + 256 * HEAP_STRIDE * sizeof(unsigned long long);

    cudaFuncSetAttribute(fps_kernel, cudaFuncAttributeMaxDynamicSharedMemorySize,
                         3 * NN * sizeof(float));
    cudaFuncSetAttribute(knn_kernel, cudaFuncAttributeMaxDynamicSharedMemorySize,
                         (int)knn_smem);

    fps_kernel<<<NB, 512, 3 * NN * sizeof(float)>>>(xyz, new_xyz);
    knn_kernel<<<NB * 8, 256, knn_smem>>>(xyz, new_xyz);
    embed_kernel<<<(NB * NS) / QPB3, 128>>>(xyz, voxels, conv_w, conv_b,
                                            ln_g, ln_b, new_xyz, out);
}